// round 1
// baseline (speedup 1.0000x reference)
#include <cuda_runtime.h>
#include <cuda_bf16.h>

// Sparsemax along last dim of a [ROWS, 32000] fp32 matrix.
//
// Algorithm (exact, no sort):
//   tau satisfies sum_i max(x_i - tau, 0) = 1.
//   Fact: tau >= rowmax - 1. Michelot iteration from tau0 = rowmax - 1:
//     tau_{k+1} = (sum_{x>tau_k} x - 1) / |{x > tau_k}|
//   is monotone non-decreasing in tau, support count strictly decreases
//   until fixed point, at which tau is exact. Output = max(x - tau, 0).
//
// One CTA per row; entire row lives in registers (1024 thr x 8 float4).

#define SMX_N        32000
#define SMX_N4       8000          // float4 elements per row
#define SMX_THREADS  1024
#define SMX_VPT      8             // float4 per thread (8*1024 = 8192 >= 8000)
#define SMX_NEG      (-3.0e38f)

__global__ __launch_bounds__(SMX_THREADS, 1)
void sparsemax_kernel(const float* __restrict__ x, float* __restrict__ y) {
    const int t    = threadIdx.x;
    const int lane = t & 31;
    const int warp = t >> 5;

    const float4* __restrict__ xr =
        reinterpret_cast<const float4*>(x + (size_t)blockIdx.x * SMX_N);
    float4* __restrict__ yr =
        reinterpret_cast<float4*>(y + (size_t)blockIdx.x * SMX_N);

    // ---- load row into registers (front-batched LDG.128, MLP=8) ----
    float4 v[SMX_VPT];
    #pragma unroll
    for (int i = 0; i < SMX_VPT; i++) {
        const int idx = i * SMX_THREADS + t;
        if (idx < SMX_N4) {
            v[i] = xr[idx];
        } else {
            v[i] = make_float4(SMX_NEG, SMX_NEG, SMX_NEG, SMX_NEG);
        }
    }

    __shared__ float s_a[32];
    __shared__ float s_b[32];
    __shared__ float s_bcast[2];

    // ---- block max reduce ----
    float m = SMX_NEG;
    #pragma unroll
    for (int i = 0; i < SMX_VPT; i++) {
        m = fmaxf(m, fmaxf(fmaxf(v[i].x, v[i].y), fmaxf(v[i].z, v[i].w)));
    }
    #pragma unroll
    for (int o = 16; o; o >>= 1)
        m = fmaxf(m, __shfl_xor_sync(0xffffffffu, m, o));
    if (lane == 0) s_a[warp] = m;
    __syncthreads();
    if (warp == 0) {
        float mm = s_a[lane];
        #pragma unroll
        for (int o = 16; o; o >>= 1)
            mm = fmaxf(mm, __shfl_xor_sync(0xffffffffu, mm, o));
        if (lane == 0) s_bcast[0] = mm;
    }
    __syncthreads();
    const float rowmax = s_bcast[0];

    // ---- Michelot iterations for exact tau ----
    float tau = rowmax - 1.0f;   // proven lower bound of true tau
    int prev_count = 0x7fffffff;

    for (int iter = 0; iter < 64; iter++) {
        float s = 0.0f;
        float c = 0.0f;
        #pragma unroll
        for (int i = 0; i < SMX_VPT; i++) {
            if (v[i].x > tau) { s += v[i].x; c += 1.0f; }
            if (v[i].y > tau) { s += v[i].y; c += 1.0f; }
            if (v[i].z > tau) { s += v[i].z; c += 1.0f; }
            if (v[i].w > tau) { s += v[i].w; c += 1.0f; }
        }
        #pragma unroll
        for (int o = 16; o; o >>= 1) {
            s += __shfl_xor_sync(0xffffffffu, s, o);
            c += __shfl_xor_sync(0xffffffffu, c, o);
        }
        if (lane == 0) { s_a[warp] = s; s_b[warp] = c; }
        __syncthreads();
        if (warp == 0) {
            float ss = s_a[lane];
            float cc = s_b[lane];
            #pragma unroll
            for (int o = 16; o; o >>= 1) {
                ss += __shfl_xor_sync(0xffffffffu, ss, o);
                cc += __shfl_xor_sync(0xffffffffu, cc, o);
            }
            if (lane == 0) {
                s_bcast[0] = (ss - 1.0f) / cc;  // new tau
                s_bcast[1] = cc;                // support count
            }
        }
        __syncthreads();
        tau = s_bcast[0];
        const int cnt = (int)s_bcast[1];
        // uniform across the block -> safe uniform break.
        // (reads of s_bcast complete before the next iteration's first
        //  __syncthreads, which precedes the next write — no hazard)
        if (cnt == prev_count) break;   // fixed point: tau exact
        prev_count = cnt;
    }

    // ---- write output: max(x - tau, 0), coalesced STG.128 ----
    #pragma unroll
    for (int i = 0; i < SMX_VPT; i++) {
        const int idx = i * SMX_THREADS + t;
        if (idx < SMX_N4) {
            float4 o;
            o.x = fmaxf(v[i].x - tau, 0.0f);
            o.y = fmaxf(v[i].y - tau, 0.0f);
            o.z = fmaxf(v[i].z - tau, 0.0f);
            o.w = fmaxf(v[i].w - tau, 0.0f);
            yr[idx] = o;
        }
    }
}

extern "C" void kernel_launch(void* const* d_in, const int* in_sizes, int n_in,
                              void* d_out, int out_size) {
    const float* x = (const float*)d_in[0];
    float* y = (float*)d_out;
    const int rows = in_sizes[0] / SMX_N;
    sparsemax_kernel<<<rows, SMX_THREADS>>>(x, y);
}

// round 2
// speedup vs baseline: 1.1375x; 1.1375x over previous
#include <cuda_runtime.h>
#include <cuda_bf16.h>
#include <cstdint>

// Sparsemax along last dim of a [ROWS, 32000] fp32 matrix.
//
// Exact, sort-free: tau solves sum_i max(x_i - tau, 0) = 1, with
// tau >= rowmax - 1. Michelot iteration tau <- (sum_{x>tau} x - 1)/|{x>tau}|
// converges to the exact tau in a few steps.
//
// Persistent kernel: grid = #SMs, each CTA processes rows bid, bid+grid, ...
// Row k+1 is prefetched into SMEM via cp.async.bulk (TMA) while row k's
// tau is computed from registers and its output is stored — keeps HBM busy
// through the compute/barrier phases.

#define SMX_N        32000
#define SMX_N4       8000          // float4 per row
#define SMX_ROWBYTES 128000
#define SMX_THREADS  1024
#define SMX_VPT      8             // float4 per thread (8*1024 >= 8000)
#define SMX_NEG      (-3.0e38f)

__device__ __forceinline__ uint32_t smx_smem_u32(const void* p) {
    uint32_t a;
    asm("{ .reg .u64 t; cvta.to.shared.u64 t, %1; cvt.u32.u64 %0, t; }"
        : "=r"(a) : "l"(p));
    return a;
}

__device__ __forceinline__ void smx_mbar_init(uint32_t mbar, uint32_t count) {
    asm volatile("mbarrier.init.shared.b64 [%0], %1;" :: "r"(mbar), "r"(count) : "memory");
}

__device__ __forceinline__ void smx_expect_tx(uint32_t mbar, uint32_t bytes) {
    asm volatile("mbarrier.arrive.expect_tx.shared.b64 _, [%0], %1;"
                 :: "r"(mbar), "r"(bytes) : "memory");
}

__device__ __forceinline__ void smx_bulk_g2s(uint32_t dst, const void* src,
                                             uint32_t bytes, uint32_t mbar) {
    asm volatile(
        "cp.async.bulk.shared::cta.global.mbarrier::complete_tx::bytes [%0], [%1], %2, [%3];"
        :: "r"(dst), "l"(src), "r"(bytes), "r"(mbar) : "memory");
}

__device__ __forceinline__ void smx_mbar_wait(uint32_t mbar, uint32_t parity) {
    asm volatile(
        "{\n\t"
        ".reg .pred P;\n\t"
        "SMXW%=:\n\t"
        "mbarrier.try_wait.parity.acquire.cta.shared::cta.b64 P, [%0], %1, 0x989680;\n\t"
        "@P bra SMXD%=;\n\t"
        "bra SMXW%=;\n\t"
        "SMXD%=:\n\t"
        "}"
        :: "r"(mbar), "r"(parity) : "memory");
}

__device__ __forceinline__ void smx_fence_async() {
    asm volatile("fence.proxy.async.shared::cta;" ::: "memory");
}

extern __shared__ float smx_buf[];   // 32000 floats = 128000 bytes

__global__ __launch_bounds__(SMX_THREADS, 1)
void sparsemax_kernel(const float* __restrict__ x, float* __restrict__ y, int rows) {
    const int t    = threadIdx.x;
    const int lane = t & 31;
    const int warp = t >> 5;
    const int stride = gridDim.x;

    __shared__ __align__(8) uint64_t s_mbar;
    __shared__ float s_a[32];
    __shared__ float s_b[32];
    __shared__ float s_bcast[2];

    const uint32_t mbar = smx_smem_u32(&s_mbar);
    const uint32_t sbuf = smx_smem_u32(smx_buf);

    if (t == 0) smx_mbar_init(mbar, 1);
    __syncthreads();

    // prologue: prefetch first row
    int row0 = blockIdx.x;
    if (t == 0 && row0 < rows) {
        smx_expect_tx(mbar, SMX_ROWBYTES);
        smx_bulk_g2s(sbuf, x + (size_t)row0 * SMX_N, SMX_ROWBYTES, mbar);
    }

    uint32_t parity = 0;

    for (int r = row0; r < rows; r += stride) {
        smx_mbar_wait(mbar, parity);
        parity ^= 1u;

        // ---- SMEM -> registers, computing the thread-local max on the fly ----
        float4 v[SMX_VPT];
        float m = SMX_NEG;
        const float4* s4 = reinterpret_cast<const float4*>(smx_buf);
        #pragma unroll
        for (int i = 0; i < SMX_VPT; i++) {
            const int idx = i * SMX_THREADS + t;
            if (idx < SMX_N4) {
                v[i] = s4[idx];
                m = fmaxf(m, fmaxf(fmaxf(v[i].x, v[i].y), fmaxf(v[i].z, v[i].w)));
            } else {
                v[i] = make_float4(SMX_NEG, SMX_NEG, SMX_NEG, SMX_NEG);
            }
        }
        __syncthreads();               // everyone done reading SMEM
        smx_fence_async();

        // ---- prefetch next row under the compute below ----
        if (t == 0 && r + stride < rows) {
            smx_expect_tx(mbar, SMX_ROWBYTES);
            smx_bulk_g2s(sbuf, x + (size_t)(r + stride) * SMX_N, SMX_ROWBYTES, mbar);
        }

        // ---- block max reduce ----
        #pragma unroll
        for (int o = 16; o; o >>= 1)
            m = fmaxf(m, __shfl_xor_sync(0xffffffffu, m, o));
        if (lane == 0) s_a[warp] = m;
        __syncthreads();
        if (warp == 0) {
            float mm = s_a[lane];
            #pragma unroll
            for (int o = 16; o; o >>= 1)
                mm = fmaxf(mm, __shfl_xor_sync(0xffffffffu, mm, o));
            if (lane == 0) s_bcast[0] = mm;
        }
        __syncthreads();
        const float rowmax = s_bcast[0];

        // ---- Michelot iterations for exact tau ----
        float tau = rowmax - 1.0f;     // proven lower bound of true tau
        int prev_count = 0x7fffffff;

        for (int iter = 0; iter < 64; iter++) {
            float s = 0.0f;
            float c = 0.0f;
            #pragma unroll
            for (int i = 0; i < SMX_VPT; i++) {
                if (v[i].x > tau) { s += v[i].x; c += 1.0f; }
                if (v[i].y > tau) { s += v[i].y; c += 1.0f; }
                if (v[i].z > tau) { s += v[i].z; c += 1.0f; }
                if (v[i].w > tau) { s += v[i].w; c += 1.0f; }
            }
            #pragma unroll
            for (int o = 16; o; o >>= 1) {
                s += __shfl_xor_sync(0xffffffffu, s, o);
                c += __shfl_xor_sync(0xffffffffu, c, o);
            }
            if (lane == 0) { s_a[warp] = s; s_b[warp] = c; }
            __syncthreads();
            if (warp == 0) {
                float ss = s_a[lane];
                float cc = s_b[lane];
                #pragma unroll
                for (int o = 16; o; o >>= 1) {
                    ss += __shfl_xor_sync(0xffffffffu, ss, o);
                    cc += __shfl_xor_sync(0xffffffffu, cc, o);
                }
                if (lane == 0) {
                    s_bcast[0] = (ss - 1.0f) / cc;  // new tau
                    s_bcast[1] = cc;                // support count
                }
            }
            __syncthreads();
            tau = s_bcast[0];
            const int cnt = (int)s_bcast[1];
            if (cnt == prev_count) break;   // fixed point: tau exact (uniform)
            prev_count = cnt;
        }

        // ---- write output: max(x - tau, 0) ----
        float4* __restrict__ yr = reinterpret_cast<float4*>(y + (size_t)r * SMX_N);
        #pragma unroll
        for (int i = 0; i < SMX_VPT; i++) {
            const int idx = i * SMX_THREADS + t;
            if (idx < SMX_N4) {
                float4 o;
                o.x = fmaxf(v[i].x - tau, 0.0f);
                o.y = fmaxf(v[i].y - tau, 0.0f);
                o.z = fmaxf(v[i].z - tau, 0.0f);
                o.w = fmaxf(v[i].w - tau, 0.0f);
                yr[idx] = o;
            }
        }
        // no extra barrier: next iteration's mbar_wait orders buffer reuse,
        // and s_a rewrites are pre-barrier-safe as analyzed.
    }
}

extern "C" void kernel_launch(void* const* d_in, const int* in_sizes, int n_in,
                              void* d_out, int out_size) {
    const float* x = (const float*)d_in[0];
    float* y = (float*)d_out;
    const int rows = in_sizes[0] / SMX_N;

    int dev = 0, sms = 148;
    cudaGetDevice(&dev);
    cudaDeviceGetAttribute(&sms, cudaDevAttrMultiProcessorCount, dev);

    static bool attr_done = false;
    if (!attr_done) {
        cudaFuncSetAttribute(sparsemax_kernel,
                             cudaFuncAttributeMaxDynamicSharedMemorySize,
                             SMX_ROWBYTES);
        attr_done = true;
    }

    int grid = rows < sms ? rows : sms;
    sparsemax_kernel<<<grid, SMX_THREADS, SMX_ROWBYTES>>>(x, y, rows);
}

// round 3
// speedup vs baseline: 1.3709x; 1.2052x over previous
#include <cuda_runtime.h>
#include <cuda_bf16.h>
#include <cstdint>

// Sparsemax along last dim of a [ROWS, 32000] fp32 matrix.
//
// Exact, sort-free. tau solves sum_i max(x_i - tau, 0) = 1 and satisfies
// tau >= rowmax - 1, so the support is a subset of C = {x > rowmax - 1}
// (~30 elements for Gaussian rows). Pipeline per row:
//   1. TMA-prefetched SMEM -> registers (fused running max)
//   2. block max-reduce
//   3. one predicate pass compacts C into SMEM (shared atomicAdd)
//   4. warp 0 runs Michelot to the fixed point on C alone (exact tau)
//   5. output pass: max(x - tau, 0)
// Next row's TMA overlaps steps 2-5.

#define SMX_N        32000
#define SMX_N4       8000
#define SMX_ROWBYTES 128000
#define SMX_THREADS  1024
#define SMX_VPT      8
#define SMX_NEG      (-3.0e38f)
#define SMX_CAP      4096          // candidate list capacity (fallback if exceeded)

__device__ __forceinline__ uint32_t smx_smem_u32(const void* p) {
    uint32_t a;
    asm("{ .reg .u64 t; cvta.to.shared.u64 t, %1; cvt.u32.u64 %0, t; }"
        : "=r"(a) : "l"(p));
    return a;
}
__device__ __forceinline__ void smx_mbar_init(uint32_t mbar, uint32_t count) {
    asm volatile("mbarrier.init.shared.b64 [%0], %1;" :: "r"(mbar), "r"(count) : "memory");
}
__device__ __forceinline__ void smx_expect_tx(uint32_t mbar, uint32_t bytes) {
    asm volatile("mbarrier.arrive.expect_tx.shared.b64 _, [%0], %1;"
                 :: "r"(mbar), "r"(bytes) : "memory");
}
__device__ __forceinline__ void smx_bulk_g2s(uint32_t dst, const void* src,
                                             uint32_t bytes, uint32_t mbar) {
    asm volatile(
        "cp.async.bulk.shared::cta.global.mbarrier::complete_tx::bytes [%0], [%1], %2, [%3];"
        :: "r"(dst), "l"(src), "r"(bytes), "r"(mbar) : "memory");
}
__device__ __forceinline__ void smx_mbar_wait(uint32_t mbar, uint32_t parity) {
    asm volatile(
        "{\n\t"
        ".reg .pred P;\n\t"
        "SMXW%=:\n\t"
        "mbarrier.try_wait.parity.acquire.cta.shared::cta.b64 P, [%0], %1, 0x989680;\n\t"
        "@P bra SMXD%=;\n\t"
        "bra SMXW%=;\n\t"
        "SMXD%=:\n\t"
        "}"
        :: "r"(mbar), "r"(parity) : "memory");
}
__device__ __forceinline__ void smx_fence_async() {
    asm volatile("fence.proxy.async.shared::cta;" ::: "memory");
}

extern __shared__ float smx_buf[];   // 32000 floats = 128000 bytes

__global__ __launch_bounds__(SMX_THREADS, 1)
void sparsemax_kernel(const float* __restrict__ x, float* __restrict__ y, int rows) {
    const int t    = threadIdx.x;
    const int lane = t & 31;
    const int warp = t >> 5;
    const int stride = gridDim.x;

    __shared__ __align__(8) uint64_t s_mbar;
    __shared__ float s_a[32];
    __shared__ float s_b[32];
    __shared__ float s_bcast[2];
    __shared__ int   s_cnt;
    __shared__ float s_cand[SMX_CAP];

    const uint32_t mbar = smx_smem_u32(&s_mbar);
    const uint32_t sbuf = smx_smem_u32(smx_buf);

    if (t == 0) smx_mbar_init(mbar, 1);
    __syncthreads();

    const int row0 = blockIdx.x;
    if (t == 0 && row0 < rows) {
        smx_expect_tx(mbar, SMX_ROWBYTES);
        smx_bulk_g2s(sbuf, x + (size_t)row0 * SMX_N, SMX_ROWBYTES, mbar);
    }

    uint32_t parity = 0;

    for (int r = row0; r < rows; r += stride) {
        smx_mbar_wait(mbar, parity);
        parity ^= 1u;

        // ---- SMEM -> registers with fused running max ----
        float4 v[SMX_VPT];
        float m = SMX_NEG;
        const float4* s4 = reinterpret_cast<const float4*>(smx_buf);
        #pragma unroll
        for (int i = 0; i < SMX_VPT; i++) {
            const int idx = i * SMX_THREADS + t;
            if (idx < SMX_N4) {
                v[i] = s4[idx];
                m = fmaxf(m, fmaxf(fmaxf(v[i].x, v[i].y), fmaxf(v[i].z, v[i].w)));
            } else {
                v[i] = make_float4(SMX_NEG, SMX_NEG, SMX_NEG, SMX_NEG);
            }
        }
        __syncthreads();               // all threads done reading the buffer
        smx_fence_async();

        // ---- prefetch next row under the compute below ----
        if (t == 0 && r + stride < rows) {
            smx_expect_tx(mbar, SMX_ROWBYTES);
            smx_bulk_g2s(sbuf, x + (size_t)(r + stride) * SMX_N, SMX_ROWBYTES, mbar);
        }

        // ---- block max reduce ----
        #pragma unroll
        for (int o = 16; o; o >>= 1)
            m = fmaxf(m, __shfl_xor_sync(0xffffffffu, m, o));
        if (lane == 0) s_a[warp] = m;
        __syncthreads();
        if (warp == 0) {
            float mm = s_a[lane];
            #pragma unroll
            for (int o = 16; o; o >>= 1)
                mm = fmaxf(mm, __shfl_xor_sync(0xffffffffu, mm, o));
            if (lane == 0) { s_bcast[0] = mm; s_cnt = 0; }
        }
        __syncthreads();
        const float thr = s_bcast[0] - 1.0f;   // tau >= thr always

        // ---- compact candidates {x > thr} into s_cand ----
        #pragma unroll
        for (int i = 0; i < SMX_VPT; i++) {
            const float a0 = v[i].x, a1 = v[i].y, a2 = v[i].z, a3 = v[i].w;
            if (a0 > thr) { int k = atomicAdd(&s_cnt, 1); if (k < SMX_CAP) s_cand[k] = a0; }
            if (a1 > thr) { int k = atomicAdd(&s_cnt, 1); if (k < SMX_CAP) s_cand[k] = a1; }
            if (a2 > thr) { int k = atomicAdd(&s_cnt, 1); if (k < SMX_CAP) s_cand[k] = a2; }
            if (a3 > thr) { int k = atomicAdd(&s_cnt, 1); if (k < SMX_CAP) s_cand[k] = a3; }
        }
        __syncthreads();
        const int cnt = s_cnt;

        if (cnt <= SMX_CAP) {
            // ---- warp 0: Michelot on the candidate list (exact tau) ----
            if (warp == 0) {
                float tau = SMX_NEG;           // first pass uses the full list
                float prevc = -1.0f;
                #pragma unroll 1
                for (int it = 0; it < 64; it++) {
                    float s = 0.0f, c = 0.0f;
                    for (int i = lane; i < cnt; i += 32) {
                        const float z = s_cand[i];
                        if (z > tau) { s += z; c += 1.0f; }
                    }
                    #pragma unroll
                    for (int o = 16; o; o >>= 1) {
                        s += __shfl_xor_sync(0xffffffffu, s, o);
                        c += __shfl_xor_sync(0xffffffffu, c, o);
                    }
                    tau = (s - 1.0f) / c;
                    if (c == prevc) break;     // fixed point
                    prevc = c;
                }
                if (lane == 0) s_bcast[0] = tau;
            }
            __syncthreads();
        } else {
            // ---- fallback: full-row Michelot (never expected in practice) ----
            float tau = thr;
            int prev_count = 0x7fffffff;
            for (int iter = 0; iter < 64; iter++) {
                float s = 0.0f, c = 0.0f;
                #pragma unroll
                for (int i = 0; i < SMX_VPT; i++) {
                    if (v[i].x > tau) { s += v[i].x; c += 1.0f; }
                    if (v[i].y > tau) { s += v[i].y; c += 1.0f; }
                    if (v[i].z > tau) { s += v[i].z; c += 1.0f; }
                    if (v[i].w > tau) { s += v[i].w; c += 1.0f; }
                }
                #pragma unroll
                for (int o = 16; o; o >>= 1) {
                    s += __shfl_xor_sync(0xffffffffu, s, o);
                    c += __shfl_xor_sync(0xffffffffu, c, o);
                }
                if (lane == 0) { s_a[warp] = s; s_b[warp] = c; }
                __syncthreads();
                if (warp == 0) {
                    float ss = s_a[lane], cc = s_b[lane];
                    #pragma unroll
                    for (int o = 16; o; o >>= 1) {
                        ss += __shfl_xor_sync(0xffffffffu, ss, o);
                        cc += __shfl_xor_sync(0xffffffffu, cc, o);
                    }
                    if (lane == 0) { s_bcast[0] = (ss - 1.0f) / cc; s_bcast[1] = cc; }
                }
                __syncthreads();
                tau = s_bcast[0];
                const int c2 = (int)s_bcast[1];
                if (c2 == prev_count) break;
                prev_count = c2;
            }
            if (t == 0) s_bcast[0] = tau;
            __syncthreads();
        }

        const float tau = s_bcast[0];

        // ---- output: max(x - tau, 0), coalesced STG.128 ----
        float4* __restrict__ yr = reinterpret_cast<float4*>(y + (size_t)r * SMX_N);
        #pragma unroll
        for (int i = 0; i < SMX_VPT; i++) {
            const int idx = i * SMX_THREADS + t;
            if (idx < SMX_N4) {
                float4 o;
                o.x = fmaxf(v[i].x - tau, 0.0f);
                o.y = fmaxf(v[i].y - tau, 0.0f);
                o.z = fmaxf(v[i].z - tau, 0.0f);
                o.w = fmaxf(v[i].w - tau, 0.0f);
                yr[idx] = o;
            }
        }
        // s_cnt/s_cand for the next row are rewritten only after two more
        // __syncthreads (max-reduce broadcast), so no WAR hazard here.
    }
}

extern "C" void kernel_launch(void* const* d_in, const int* in_sizes, int n_in,
                              void* d_out, int out_size) {
    const float* x = (const float*)d_in[0];
    float* y = (float*)d_out;
    const int rows = in_sizes[0] / SMX_N;

    int dev = 0, sms = 148;
    cudaGetDevice(&dev);
    cudaDeviceGetAttribute(&sms, cudaDevAttrMultiProcessorCount, dev);

    static bool attr_done = false;
    if (!attr_done) {
        cudaFuncSetAttribute(sparsemax_kernel,
                             cudaFuncAttributeMaxDynamicSharedMemorySize,
                             SMX_ROWBYTES);
        attr_done = true;
    }

    int grid = rows < sms ? rows : sms;
    sparsemax_kernel<<<grid, SMX_THREADS, SMX_ROWBYTES>>>(x, y, rows);
}